// round 1
// baseline (speedup 1.0000x reference)
#include <cuda_runtime.h>
#include <cuda_bf16.h>
#include <math.h>

#define BATCH 16384
#define KDIM 128
#define CLS 32
#define SPC 129            // smem pitch (conflict-free for column walks)
#define RCHUNK 8
#define ROWS_PER_CHUNK (BATCH / RCHUNK)   // 2048

// ---------------- scratch (device globals: allocation-free) ----------------
__device__ float g_sum[CLS * KDIM];
__device__ int   g_cnt[CLS];
__device__ int   g_first[CLS];
__device__ float g_G[CLS * KDIM * KDIM];    // per-class Gram sums (2 MB)
__device__ float g_S[CLS * KDIM * KDIM];    // per-class scatter+I (2 MB)
__device__ float g_inv[CLS * KDIM * KDIM];  // per-class inverse (2 MB)
__device__ float g_mu[CLS * KDIM];
__device__ float g_ld2[CLS];

// ---------------- K0: zero scratch + output ----------------
__global__ void k_init(float* out) {
    int i = blockIdx.x * blockDim.x + threadIdx.x;
    if (i < CLS * KDIM * KDIM) g_G[i] = 0.0f;
    if (i < CLS * KDIM) g_sum[i] = 0.0f;
    if (i < CLS) { g_cnt[i] = 0; g_first[i] = BATCH; }
    if (i == 0) out[0] = 0.0f;
}

// ---------------- K1: class sums, counts, first occurrence ----------------
__global__ void k_sums(const float* __restrict__ feat, const int* __restrict__ lab) {
    __shared__ float ssum[CLS * KDIM];   // 16 KB
    __shared__ int   scnt[CLS];
    int tid = threadIdx.x;               // 256 threads
    for (int i = tid; i < CLS * KDIM; i += 256) ssum[i] = 0.0f;
    if (tid < CLS) scnt[tid] = 0;
    __syncthreads();

    int warp = tid >> 5, lane = tid & 31;
    int r0 = blockIdx.x * 256 + warp * 32;   // 64 blocks x 256 rows
    for (int r = r0; r < r0 + 32; r++) {
        int c = lab[r];
        if (lane == 0) { atomicAdd(&scnt[c], 1); atomicMin(&g_first[c], r); }
        float4 v = ((const float4*)(feat + (size_t)r * KDIM))[lane];
        float* dst = &ssum[c * KDIM + lane * 4];
        atomicAdd(dst + 0, v.x);
        atomicAdd(dst + 1, v.y);
        atomicAdd(dst + 2, v.z);
        atomicAdd(dst + 3, v.w);
    }
    __syncthreads();
    for (int i = tid; i < CLS * KDIM; i += 256) atomicAdd(&g_sum[i], ssum[i]);
    if (tid < CLS) atomicAdd(&g_cnt[tid], scnt[tid]);
}

// ---------------- K2: per-class Gram accumulation G_c = sum x x^T ----------
__global__ __launch_bounds__(256) void k_scatter(const float* __restrict__ feat,
                                                 const int* __restrict__ lab) {
    const int c = blockIdx.y;
    const int chunk = blockIdx.x;
    const int R0 = chunk * ROWS_PER_CHUNK;
    __shared__ int s_idx[ROWS_PER_CHUNK];     // 8 KB worst case
    __shared__ int s_n;
    __shared__ __align__(16) float s_x[16][KDIM];   // 8 KB tile of rows
    int tid = threadIdx.x;
    if (tid == 0) s_n = 0;
    __syncthreads();

    for (int r = R0 + tid; r < R0 + ROWS_PER_CHUNK; r += 256) {
        if (lab[r] == c) { int p = atomicAdd(&s_n, 1); s_idx[p] = r; }
    }
    __syncthreads();
    int n = s_n;

    float acc[8][8];
#pragma unroll
    for (int u = 0; u < 8; u++)
#pragma unroll
        for (int v = 0; v < 8; v++) acc[u][v] = 0.0f;

    int ty = tid >> 4, tx = tid & 15;   // 16x16 thread grid, 8x8 tile each

    for (int t = 0; t < n; t += 16) {
        int m = min(16, n - t);
        // load m rows cooperatively (m*32 float4s)
        for (int i = tid; i < m * 32; i += 256) {
            int rr = i >> 5, q = i & 31;
            ((float4*)s_x[rr])[q] =
                ((const float4*)(feat + (size_t)s_idx[t + rr] * KDIM))[q];
        }
        __syncthreads();
        for (int e = 0; e < m; e++) {
            float a[8], b[8];
#pragma unroll
            for (int u = 0; u < 8; u++) { a[u] = s_x[e][ty * 8 + u]; b[u] = s_x[e][tx * 8 + u]; }
#pragma unroll
            for (int u = 0; u < 8; u++)
#pragma unroll
                for (int v = 0; v < 8; v++) acc[u][v] = fmaf(a[u], b[v], acc[u][v]);
        }
        __syncthreads();
    }

    if (n > 0) {
        float* G = g_G + (size_t)c * KDIM * KDIM;
#pragma unroll
        for (int u = 0; u < 8; u++)
#pragma unroll
            for (int v = 0; v < 8; v++)
                atomicAdd(&G[(ty * 8 + u) * KDIM + (tx * 8 + v)], acc[u][v]);
    }
}

// ---------------- K3: per-class S, Cholesky, logdet, inverse ---------------
__global__ __launch_bounds__(256, 1) void k_chol() {
    extern __shared__ float sm[];
    float* sS = sm;                      // KDIM * SPC
    float* sY = sm + KDIM * SPC;         // KDIM * SPC
    __shared__ float s_mu[KDIM];
    __shared__ float sred[256];
    int c = blockIdx.x, tid = threadIdx.x;

    float n = (float)g_cnt[c];
    float rn = 1.0f / n;
    if (tid < KDIM) {
        float m = g_sum[c * KDIM + tid] * rn;
        s_mu[tid] = m;
        g_mu[c * KDIM + tid] = m;
    }
    __syncthreads();

    const float* G = g_G + (size_t)c * KDIM * KDIM;
    float* Sg = g_S + (size_t)c * KDIM * KDIM;
    for (int idx = tid; idx < KDIM * KDIM; idx += 256) {
        int a = idx >> 7, b = idx & 127;
        float s = G[idx] * rn - s_mu[a] * s_mu[b] + (a == b ? 1.0f : 0.0f);
        sS[a * SPC + b] = s;
        Sg[idx] = s;
    }
    __syncthreads();

    // Right-looking Cholesky (lower), 2 threads per row on trailing update
    for (int j = 0; j < KDIM; j++) {
        float pivot = sS[j * SPC + j];
        float d = sqrtf(pivot);
        float rd = 1.0f / d;
        __syncthreads();                 // all threads read pivot before write
        if (tid == 0) sS[j * SPC + j] = d;
        if (tid > j && tid < KDIM) sS[tid * SPC + j] *= rd;
        __syncthreads();                 // column j final
        int i = tid >> 1;
        if (i > j && i < KDIM) {
            float lij = sS[i * SPC + j];
            for (int k = j + 1 + (tid & 1); k <= i; k += 2)
                sS[i * SPC + k] -= lij * sS[k * SPC + j];
        }
        __syncthreads();                 // trailing done before next pivot read
    }

    // log2 det = 2 * sum log2(diag)
    float v = (tid < KDIM) ? log2f(sS[tid * SPC + tid]) : 0.0f;
    sred[tid] = v;
    __syncthreads();
    for (int s = 128; s; s >>= 1) { if (tid < s) sred[tid] += sred[tid + s]; __syncthreads(); }
    if (tid == 0) g_ld2[c] = 2.0f * sred[0];

    // Forward substitution: Y = L^{-1} (column t per thread)
    if (tid < KDIM) {
        int t = tid;
        for (int j = t; j < KDIM; j++) {
            float s0 = 0.f, s1 = 0.f, s2 = 0.f, s3 = 0.f;
            int m = t;
            for (; m + 3 < j; m += 4) {
                s0 += sS[j * SPC + m]     * sY[m * SPC + t];
                s1 += sS[j * SPC + m + 1] * sY[(m + 1) * SPC + t];
                s2 += sS[j * SPC + m + 2] * sY[(m + 2) * SPC + t];
                s3 += sS[j * SPC + m + 3] * sY[(m + 3) * SPC + t];
            }
            for (; m < j; m++) s0 += sS[j * SPC + m] * sY[m * SPC + t];
            float rhs = ((j == t) ? 1.0f : 0.0f) - (s0 + s1 + s2 + s3);
            sY[j * SPC + t] = rhs / sS[j * SPC + j];
        }
    }
    __syncthreads();

    // inv = Y^T Y (symmetric): inv[a][b] = sum_{m>=b} Y[m][a]*Y[m][b], b >= a
    float* Ig = g_inv + (size_t)c * KDIM * KDIM;
    for (int idx = tid; idx < KDIM * KDIM; idx += 256) {
        int a = idx >> 7, b = idx & 127;
        if (b < a) continue;
        float s0 = 0.f, s1 = 0.f;
        int m = b;
        for (; m + 1 < KDIM; m += 2) {
            s0 += sY[m * SPC + a] * sY[m * SPC + b];
            s1 += sY[(m + 1) * SPC + a] * sY[(m + 1) * SPC + b];
        }
        if (m < KDIM) s0 += sY[m * SPC + a] * sY[m * SPC + b];
        float s = s0 + s1;
        Ig[a * KDIM + b] = s;
        Ig[b * KDIM + a] = s;
    }
}

// ---------------- K4: pairwise KL + mask + final reduction -----------------
__global__ void k_final(float* out) {
    int i = blockIdx.x >> 5, j = blockIdx.x & 31;
    int tid = threadIdx.x;
    __shared__ float sv[KDIM];
    __shared__ float2 sred[256];
    __shared__ int smask;

    if (tid == 0) {
        int fi = g_first[i], fj = g_first[j], ri = 0, rj = 0;
        for (int c = 0; c < CLS; c++) { int f = g_first[c]; ri += (f < fi); rj += (f < fj); }
        smask = (ri <= CLS - 2) && (rj >= 1);
    }
    if (tid < KDIM) sv[tid] = g_mu[i * KDIM + tid] - g_mu[j * KDIM + tid];
    __syncthreads();

    float tr = 0.0f, qd = 0.0f;
    if (smask) {
        const float* Sp = g_S + (size_t)i * KDIM * KDIM;
        const float* Ip = g_inv + (size_t)j * KDIM * KDIM;
        for (int idx = tid; idx < KDIM * KDIM; idx += 256) {
            float w = Ip[idx];
            tr += w * Sp[idx];                       // tr(inv_j S_i), both symmetric
            qd += w * sv[idx >> 7] * sv[idx & 127];  // diff^T inv_j diff
        }
    }
    sred[tid] = make_float2(tr, qd);
    __syncthreads();
    for (int s = 128; s; s >>= 1) {
        if (tid < s) { sred[tid].x += sred[tid + s].x; sred[tid].y += sred[tid + s].y; }
        __syncthreads();
    }
    if (tid == 0 && smask) {
        float kl = 0.5f * ((g_ld2[j] - g_ld2[i]) - (float)KDIM + sred[0].y + sred[0].x);
        atomicAdd(out, kl);
    }

    if (blockIdx.x == 0) {
        __syncthreads();
        float m2 = 0.0f;
        for (int idx = tid; idx < CLS * KDIM; idx += 256) { float m = g_mu[idx]; m2 += m * m; }
        sred[tid].x = m2;
        __syncthreads();
        for (int s = 128; s; s >>= 1) { if (tid < s) sred[tid].x += sred[tid + s].x; __syncthreads(); }
        if (tid == 0) atomicAdd(out, -sred[0].x);
    }
}

// ---------------- launch ----------------
extern "C" void kernel_launch(void* const* d_in, const int* in_sizes, int n_in,
                              void* d_out, int out_size) {
    const float* feat = (const float*)d_in[0];
    const int*   lab  = (const int*)d_in[1];
    float* out = (float*)d_out;

    const int CHOL_SMEM = 2 * KDIM * SPC * (int)sizeof(float);  // 132096 B
    cudaFuncSetAttribute(k_chol, cudaFuncAttributeMaxDynamicSharedMemorySize, CHOL_SMEM);

    k_init<<<(CLS * KDIM * KDIM + 255) / 256, 256>>>(out);
    k_sums<<<BATCH / 256, 256>>>(feat, lab);
    k_scatter<<<dim3(RCHUNK, CLS), 256>>>(feat, lab);
    k_chol<<<CLS, 256, CHOL_SMEM>>>();
    k_final<<<CLS * CLS, 256>>>(out);
}

// round 2
// speedup vs baseline: 1.3527x; 1.3527x over previous
#include <cuda_runtime.h>
#include <cuda_bf16.h>
#include <math.h>

#define BATCH 16384
#define KDIM 128
#define CLS 32
#define SPC 129            // sS pitch (odd -> conflict-free column walks)
#define YP  132            // sYt pitch (mult of 4 -> float4 rows)
#define PPITCH 100         // transposed-panel pitch (mult of 4)
#define NB 32
#define RCHUNK 8
#define ROWS_PER_CHUNK (BATCH / RCHUNK)   // 2048

// ---------------- scratch (device globals: allocation-free) ----------------
__device__ float g_sum[CLS * KDIM];
__device__ int   g_cnt[CLS];
__device__ int   g_first[CLS];
__device__ float g_G[CLS * KDIM * KDIM];    // per-class Gram sums (2 MB)
__device__ float g_S[CLS * KDIM * KDIM];    // per-class scatter+I (2 MB)
__device__ float g_inv[CLS * KDIM * KDIM];  // per-class inverse (2 MB)
__device__ float g_mu[CLS * KDIM];
__device__ float g_ld2[CLS];

// ---------------- K0: zero scratch + output ----------------
__global__ void k_init(float* out) {
    int i = blockIdx.x * blockDim.x + threadIdx.x;
    if (i < CLS * KDIM * KDIM) g_G[i] = 0.0f;
    if (i < CLS * KDIM) g_sum[i] = 0.0f;
    if (i < CLS) { g_cnt[i] = 0; g_first[i] = BATCH; }
    if (i == 0) out[0] = 0.0f;
}

// ---------------- K1: class sums, counts, first occurrence ----------------
__global__ void k_sums(const float* __restrict__ feat, const int* __restrict__ lab) {
    __shared__ float ssum[CLS * KDIM];   // 16 KB
    __shared__ int   scnt[CLS];
    int tid = threadIdx.x;               // 256 threads
    for (int i = tid; i < CLS * KDIM; i += 256) ssum[i] = 0.0f;
    if (tid < CLS) scnt[tid] = 0;
    __syncthreads();

    int warp = tid >> 5, lane = tid & 31;
    int r0 = blockIdx.x * 256 + warp * 32;   // 64 blocks x 256 rows
    for (int r = r0; r < r0 + 32; r++) {
        int c = lab[r];
        if (lane == 0) { atomicAdd(&scnt[c], 1); atomicMin(&g_first[c], r); }
        float4 v = ((const float4*)(feat + (size_t)r * KDIM))[lane];
        float* dst = &ssum[c * KDIM + lane * 4];
        atomicAdd(dst + 0, v.x);
        atomicAdd(dst + 1, v.y);
        atomicAdd(dst + 2, v.z);
        atomicAdd(dst + 3, v.w);
    }
    __syncthreads();
    for (int i = tid; i < CLS * KDIM; i += 256) atomicAdd(&g_sum[i], ssum[i]);
    if (tid < CLS) atomicAdd(&g_cnt[tid], scnt[tid]);
}

// ---------------- K2: per-class Gram accumulation G_c = sum x x^T ----------
__global__ __launch_bounds__(256) void k_scatter(const float* __restrict__ feat,
                                                 const int* __restrict__ lab) {
    const int c = blockIdx.y;
    const int chunk = blockIdx.x;
    const int R0 = chunk * ROWS_PER_CHUNK;
    __shared__ int s_idx[ROWS_PER_CHUNK];     // 8 KB worst case
    __shared__ int s_n;
    __shared__ __align__(16) float s_x[16][KDIM];   // 8 KB tile of rows
    int tid = threadIdx.x;
    if (tid == 0) s_n = 0;
    __syncthreads();

    for (int r = R0 + tid; r < R0 + ROWS_PER_CHUNK; r += 256) {
        if (lab[r] == c) { int p = atomicAdd(&s_n, 1); s_idx[p] = r; }
    }
    __syncthreads();
    int n = s_n;

    float acc[8][8];
#pragma unroll
    for (int u = 0; u < 8; u++)
#pragma unroll
        for (int v = 0; v < 8; v++) acc[u][v] = 0.0f;

    int ty = tid >> 4, tx = tid & 15;   // 16x16 thread grid, 8x8 tile each

    for (int t = 0; t < n; t += 16) {
        int m = min(16, n - t);
        for (int i = tid; i < m * 32; i += 256) {
            int rr = i >> 5, q = i & 31;
            ((float4*)s_x[rr])[q] =
                ((const float4*)(feat + (size_t)s_idx[t + rr] * KDIM))[q];
        }
        __syncthreads();
        for (int e = 0; e < m; e++) {
            float a[8], b[8];
#pragma unroll
            for (int u = 0; u < 8; u++) { a[u] = s_x[e][ty * 8 + u]; b[u] = s_x[e][tx * 8 + u]; }
#pragma unroll
            for (int u = 0; u < 8; u++)
#pragma unroll
                for (int v = 0; v < 8; v++) acc[u][v] = fmaf(a[u], b[v], acc[u][v]);
        }
        __syncthreads();
    }

    if (n > 0) {
        float* G = g_G + (size_t)c * KDIM * KDIM;
#pragma unroll
        for (int u = 0; u < 8; u++)
#pragma unroll
            for (int v = 0; v < 8; v++)
                atomicAdd(&G[(ty * 8 + u) * KDIM + (tx * 8 + v)], acc[u][v]);
    }
}

// ---------------- K3: per-class S, blocked Cholesky, logdet, inverse -------
__global__ __launch_bounds__(256, 1) void k_chol() {
    extern __shared__ float sm[];
    float* sS  = sm;                       // KDIM * SPC
    float* sYt = sm + KDIM * SPC;          // KDIM * YP (Y transposed: sYt[col][row])
    __shared__ __align__(16) float sPT[NB * PPITCH];  // transposed panel
    __shared__ float sRD[KDIM];            // reciprocal diag of L
    __shared__ float s_mu[KDIM];
    __shared__ float sred[256];
    int c = blockIdx.x, tid = threadIdx.x;

    float n = (float)g_cnt[c];
    float rn = 1.0f / n;
    if (tid < KDIM) {
        float m = g_sum[c * KDIM + tid] * rn;
        s_mu[tid] = m;
        g_mu[c * KDIM + tid] = m;
    }
    __syncthreads();

    const float* G = g_G + (size_t)c * KDIM * KDIM;
    float* Sg = g_S + (size_t)c * KDIM * KDIM;
    for (int idx = tid; idx < KDIM * KDIM; idx += 256) {
        int a = idx >> 7, b = idx & 127;
        float s = G[idx] * rn - s_mu[a] * s_mu[b] + (a == b ? 1.0f : 0.0f);
        sS[a * SPC + b] = s;
        Sg[idx] = s;
    }
    // zero sYt while we're here (upper part must be 0 for YtY)
    for (int idx = tid; idx < KDIM * YP; idx += 256) sYt[idx] = 0.0f;
    __syncthreads();

    // ---- blocked right-looking Cholesky, NB=32 ----
    for (int kb = 0; kb < KDIM / NB; kb++) {
        const int c0 = kb * NB;

        // 1) 32x32 diagonal block factorization in warp 0 registers
        if (tid < 32) {
            const int lane = tid;
            const int row = c0 + lane;
            float a[NB];
#pragma unroll
            for (int m = 0; m < NB; m++) a[m] = sS[row * SPC + c0 + m];
#pragma unroll
            for (int j = 0; j < NB; j++) {
                float piv = __shfl_sync(0xffffffffu, a[j], j);
                float d = sqrtf(piv);
                float rd = 1.0f / d;
                if (lane == j) { a[j] = d; sRD[c0 + j] = rd; }
                else if (lane > j) a[j] *= rd;
                float lj = a[j];    // L[lane][j] (valid for lane >= j)
#pragma unroll
                for (int m = j + 1; m < NB; m++) {
                    float lmj = __shfl_sync(0xffffffffu, lj, m);
                    if (lane >= m) a[m] -= lj * lmj;
                }
            }
#pragma unroll
            for (int m = 0; m < NB; m++)
                if (lane >= m) sS[row * SPC + c0 + m] = a[m];
        }
        __syncthreads();

        const int M = KDIM - c0 - NB;   // rows below diag block: 96,64,32,0

        // 2) panel solve: one thread per row, fully unrolled triangular solve
        if (tid < M) {
            const int r = c0 + NB + tid;
            float x[NB];
#pragma unroll
            for (int j = 0; j < NB; j++) {
                float s = sS[r * SPC + c0 + j];
                float s1 = 0.0f;
#pragma unroll
                for (int m = 0; m + 1 < j; m += 2) {
                    s  -= x[m]     * sS[(c0 + j) * SPC + c0 + m];
                    s1 -= x[m + 1] * sS[(c0 + j) * SPC + c0 + m + 1];
                }
                if (j & 1) s -= x[j - 1] * sS[(c0 + j) * SPC + c0 + j - 1];
                s = (s + s1) * sRD[c0 + j];
                x[j] = s;
                sS[r * SPC + c0 + j] = s;
                sPT[j * PPITCH + tid] = s;   // transposed panel
            }
        }
        __syncthreads();

        // 3) trailing SYRK update: lower tiles only, 4x4 per thread, float4 loads
        if (M > 0) {
            const int T = M >> 2;
            const int ntile = T * (T + 1) / 2;
            const int r0 = c0 + NB;
            for (int t = tid; t < ntile; t += 256) {
                int tI = (int)(sqrtf(2.0f * t + 0.25f) - 0.5f);
                while ((tI + 1) * (tI + 2) / 2 <= t) tI++;
                while (tI * (tI + 1) / 2 > t) tI--;
                int tJ = t - tI * (tI + 1) / 2;
                int i0 = tI * 4, j0 = tJ * 4;
                float acc[4][4];
#pragma unroll
                for (int u = 0; u < 4; u++)
#pragma unroll
                    for (int v = 0; v < 4; v++) acc[u][v] = 0.0f;
                for (int m = 0; m < NB; m++) {
                    float4 av = *(const float4*)&sPT[m * PPITCH + i0];
                    float4 bv = *(const float4*)&sPT[m * PPITCH + j0];
                    float aa[4] = {av.x, av.y, av.z, av.w};
                    float bb[4] = {bv.x, bv.y, bv.z, bv.w};
#pragma unroll
                    for (int u = 0; u < 4; u++)
#pragma unroll
                        for (int v = 0; v < 4; v++)
                            acc[u][v] = fmaf(aa[u], bb[v], acc[u][v]);
                }
#pragma unroll
                for (int u = 0; u < 4; u++)
#pragma unroll
                    for (int v = 0; v < 4; v++)
                        sS[(r0 + i0 + u) * SPC + r0 + j0 + v] -= acc[u][v];
            }
        }
        __syncthreads();
    }

    // ---- log2 det = 2 * sum log2(diag) ----
    float v = (tid < KDIM) ? log2f(sS[tid * SPC + tid]) : 0.0f;
    sred[tid] = v;
    __syncthreads();
    for (int s = 128; s; s >>= 1) { if (tid < s) sred[tid] += sred[tid + s]; __syncthreads(); }
    if (tid == 0) g_ld2[c] = 2.0f * sred[0];

    // ---- forward substitution: Y = L^{-1}, stored transposed (sYt[col][row]) --
    if (tid < KDIM) {
        const int t = tid;
        float* yr = &sYt[t * YP];
        for (int j = t; j < KDIM; j++) {
            const float* Lr = &sS[j * SPC];
            float s0 = 0.f, s1 = 0.f, s2 = 0.f, s3 = 0.f;
            int m = t;
            for (; m + 3 < j; m += 4) {
                s0 += Lr[m]     * yr[m];
                s1 += Lr[m + 1] * yr[m + 1];
                s2 += Lr[m + 2] * yr[m + 2];
                s3 += Lr[m + 3] * yr[m + 3];
            }
            for (; m < j; m++) s0 += Lr[m] * yr[m];
            float rhs = ((j == t) ? 1.0f : 0.0f) - ((s0 + s1) + (s2 + s3));
            yr[j] = rhs * sRD[j];
        }
    }
    __syncthreads();

    // ---- inv = Y^T Y, 4x4 tiles over upper triangle, float4 along rows ----
    float* Ig = g_inv + (size_t)c * KDIM * KDIM;
    {
        const int T = KDIM >> 2;                  // 32
        const int ntile = T * (T + 1) / 2;        // 528
        for (int t = tid; t < ntile; t += 256) {
            int tB = (int)(sqrtf(2.0f * t + 0.25f) - 0.5f);
            while ((tB + 1) * (tB + 2) / 2 <= t) tB++;
            while (tB * (tB + 1) / 2 > t) tB--;
            int tS = t - tB * (tB + 1) / 2;
            int a0 = tS * 4, b0 = tB * 4;          // b0 >= a0
            float acc[4][4];
#pragma unroll
            for (int u = 0; u < 4; u++)
#pragma unroll
                for (int v = 0; v < 4; v++) acc[u][v] = 0.0f;
            for (int m = b0; m < KDIM; m += 4) {
                float4 A[4], B[4];
#pragma unroll
                for (int u = 0; u < 4; u++) A[u] = *(const float4*)&sYt[(a0 + u) * YP + m];
#pragma unroll
                for (int v = 0; v < 4; v++) B[v] = *(const float4*)&sYt[(b0 + v) * YP + m];
#pragma unroll
                for (int u = 0; u < 4; u++)
#pragma unroll
                    for (int v = 0; v < 4; v++)
                        acc[u][v] += A[u].x * B[v].x + A[u].y * B[v].y
                                   + A[u].z * B[v].z + A[u].w * B[v].w;
            }
#pragma unroll
            for (int u = 0; u < 4; u++)
#pragma unroll
                for (int v = 0; v < 4; v++) {
                    Ig[(a0 + u) * KDIM + (b0 + v)] = acc[u][v];
                    Ig[(b0 + v) * KDIM + (a0 + u)] = acc[u][v];
                }
        }
    }
}

// ---------------- K4: pairwise KL + mask + final reduction -----------------
__global__ void k_final(float* out) {
    int i = blockIdx.x >> 5, j = blockIdx.x & 31;
    int tid = threadIdx.x;
    __shared__ float sv[KDIM];
    __shared__ float2 sred[256];
    __shared__ int smask;

    if (tid == 0) {
        int fi = g_first[i], fj = g_first[j], ri = 0, rj = 0;
        for (int c = 0; c < CLS; c++) { int f = g_first[c]; ri += (f < fi); rj += (f < fj); }
        smask = (ri <= CLS - 2) && (rj >= 1);
    }
    if (tid < KDIM) sv[tid] = g_mu[i * KDIM + tid] - g_mu[j * KDIM + tid];
    __syncthreads();

    float tr = 0.0f, qd = 0.0f;
    if (smask) {
        const float* Sp = g_S + (size_t)i * KDIM * KDIM;
        const float* Ip = g_inv + (size_t)j * KDIM * KDIM;
        for (int idx = tid; idx < KDIM * KDIM; idx += 256) {
            float w = Ip[idx];
            tr += w * Sp[idx];                       // tr(inv_j S_i)
            qd += w * sv[idx >> 7] * sv[idx & 127];  // diff^T inv_j diff
        }
    }
    sred[tid] = make_float2(tr, qd);
    __syncthreads();
    for (int s = 128; s; s >>= 1) {
        if (tid < s) { sred[tid].x += sred[tid + s].x; sred[tid].y += sred[tid + s].y; }
        __syncthreads();
    }
    if (tid == 0 && smask) {
        float kl = 0.5f * ((g_ld2[j] - g_ld2[i]) - (float)KDIM + sred[0].y + sred[0].x);
        atomicAdd(out, kl);
    }

    if (blockIdx.x == 0) {
        __syncthreads();
        float m2 = 0.0f;
        for (int idx = tid; idx < CLS * KDIM; idx += 256) { float m = g_mu[idx]; m2 += m * m; }
        sred[tid].x = m2;
        __syncthreads();
        for (int s = 128; s; s >>= 1) { if (tid < s) sred[tid].x += sred[tid + s].x; __syncthreads(); }
        if (tid == 0) atomicAdd(out, -sred[0].x);
    }
}

// ---------------- launch ----------------
extern "C" void kernel_launch(void* const* d_in, const int* in_sizes, int n_in,
                              void* d_out, int out_size) {
    const float* feat = (const float*)d_in[0];
    const int*   lab  = (const int*)d_in[1];
    float* out = (float*)d_out;

    const int CHOL_SMEM = (KDIM * SPC + KDIM * YP) * (int)sizeof(float);  // 133632 B
    cudaFuncSetAttribute(k_chol, cudaFuncAttributeMaxDynamicSharedMemorySize, CHOL_SMEM);

    k_init<<<(CLS * KDIM * KDIM + 255) / 256, 256>>>(out);
    k_sums<<<BATCH / 256, 256>>>(feat, lab);
    k_scatter<<<dim3(RCHUNK, CLS), 256>>>(feat, lab);
    k_chol<<<CLS, 256, CHOL_SMEM>>>();
    k_final<<<CLS * CLS, 256>>>(out);
}

// round 3
// speedup vs baseline: 1.6364x; 1.2097x over previous
#include <cuda_runtime.h>
#include <cuda_bf16.h>
#include <math.h>

#define BATCH 16384
#define KDIM 128
#define CLS 32
#define SPC 129            // sS pitch (odd -> conflict-free column walks)
#define YP  132            // sYt pitch (mult of 4 -> float4 rows)
#define PPITCH 100         // transposed-panel pitch (mult of 4)
#define TP 36              // 32x32 tile pitch (mult of 4)
#define NB 32
#define RCHUNK 8
#define ROWS_PER_CHUNK (BATCH / RCHUNK)   // 2048

// ---------------- scratch (device globals: allocation-free) ----------------
__device__ float g_sum[CLS * KDIM];
__device__ int   g_cnt[CLS];
__device__ int   g_first[CLS];
__device__ float g_G[CLS * KDIM * KDIM];    // per-class Gram sums
__device__ float g_S[CLS * KDIM * KDIM];    // per-class scatter+I
__device__ float g_L[CLS * KDIM * KDIM];    // per-class Cholesky factor
__device__ float g_Yt[CLS * KDIM * KDIM];   // per-class L^{-1}, transposed [col][row]
__device__ float g_inv[CLS * KDIM * KDIM];  // per-class inverse
__device__ float g_mu[CLS * KDIM];
__device__ float g_ld2[CLS];

// ---------------- K0: zero scratch + output ----------------
__global__ void k_init(float* out) {
    int i = blockIdx.x * blockDim.x + threadIdx.x;
    if (i < CLS * KDIM * KDIM) g_G[i] = 0.0f;
    if (i < CLS * KDIM) g_sum[i] = 0.0f;
    if (i < CLS) { g_cnt[i] = 0; g_first[i] = BATCH; }
    if (i == 0) out[0] = 0.0f;
}

// ---------------- K1: class sums, counts, first occurrence ----------------
__global__ void k_sums(const float* __restrict__ feat, const int* __restrict__ lab) {
    __shared__ float ssum[CLS * KDIM];   // 16 KB
    __shared__ int   scnt[CLS];
    int tid = threadIdx.x;               // 256 threads
    for (int i = tid; i < CLS * KDIM; i += 256) ssum[i] = 0.0f;
    if (tid < CLS) scnt[tid] = 0;
    __syncthreads();

    int warp = tid >> 5, lane = tid & 31;
    int r0 = blockIdx.x * 256 + warp * 32;   // 64 blocks x 256 rows
    for (int r = r0; r < r0 + 32; r++) {
        int c = lab[r];
        if (lane == 0) { atomicAdd(&scnt[c], 1); atomicMin(&g_first[c], r); }
        float4 v = ((const float4*)(feat + (size_t)r * KDIM))[lane];
        float* dst = &ssum[c * KDIM + lane * 4];
        atomicAdd(dst + 0, v.x);
        atomicAdd(dst + 1, v.y);
        atomicAdd(dst + 2, v.z);
        atomicAdd(dst + 3, v.w);
    }
    __syncthreads();
    for (int i = tid; i < CLS * KDIM; i += 256) atomicAdd(&g_sum[i], ssum[i]);
    if (tid < CLS) atomicAdd(&g_cnt[tid], scnt[tid]);
}

// ---------------- K2: per-class Gram accumulation G_c = sum x x^T ----------
__global__ __launch_bounds__(256) void k_scatter(const float* __restrict__ feat,
                                                 const int* __restrict__ lab) {
    const int c = blockIdx.y;
    const int chunk = blockIdx.x;
    const int R0 = chunk * ROWS_PER_CHUNK;
    __shared__ int s_idx[ROWS_PER_CHUNK];
    __shared__ int s_n;
    __shared__ __align__(16) float s_x[16][KDIM];
    int tid = threadIdx.x;
    if (tid == 0) s_n = 0;
    __syncthreads();

    for (int r = R0 + tid; r < R0 + ROWS_PER_CHUNK; r += 256) {
        if (lab[r] == c) { int p = atomicAdd(&s_n, 1); s_idx[p] = r; }
    }
    __syncthreads();
    int n = s_n;

    float acc[8][8];
#pragma unroll
    for (int u = 0; u < 8; u++)
#pragma unroll
        for (int v = 0; v < 8; v++) acc[u][v] = 0.0f;

    int ty = tid >> 4, tx = tid & 15;

    for (int t = 0; t < n; t += 16) {
        int m = min(16, n - t);
        for (int i = tid; i < m * 32; i += 256) {
            int rr = i >> 5, q = i & 31;
            ((float4*)s_x[rr])[q] =
                ((const float4*)(feat + (size_t)s_idx[t + rr] * KDIM))[q];
        }
        __syncthreads();
        for (int e = 0; e < m; e++) {
            float a[8], b[8];
#pragma unroll
            for (int u = 0; u < 8; u++) { a[u] = s_x[e][ty * 8 + u]; b[u] = s_x[e][tx * 8 + u]; }
#pragma unroll
            for (int u = 0; u < 8; u++)
#pragma unroll
                for (int v = 0; v < 8; v++) acc[u][v] = fmaf(a[u], b[v], acc[u][v]);
        }
        __syncthreads();
    }

    if (n > 0) {
        float* G = g_G + (size_t)c * KDIM * KDIM;
#pragma unroll
        for (int u = 0; u < 8; u++)
#pragma unroll
            for (int v = 0; v < 8; v++)
                atomicAdd(&G[(ty * 8 + u) * KDIM + (tx * 8 + v)], acc[u][v]);
    }
}

// ---------------- K3a: per-class S, blocked Cholesky, logdet, store L ------
__global__ __launch_bounds__(256, 1) void k_cholA() {
    extern __shared__ float sm[];
    float* sS = sm;                        // KDIM * SPC
    __shared__ __align__(16) float sPT[NB * PPITCH];
    __shared__ float sRD[KDIM];
    __shared__ float s_mu[KDIM];
    __shared__ float sred[256];
    int c = blockIdx.x, tid = threadIdx.x;

    float n = (float)g_cnt[c];
    float rn = 1.0f / n;
    if (tid < KDIM) {
        float m = g_sum[c * KDIM + tid] * rn;
        s_mu[tid] = m;
        g_mu[c * KDIM + tid] = m;
    }
    __syncthreads();

    const float* G = g_G + (size_t)c * KDIM * KDIM;
    float* Sg = g_S + (size_t)c * KDIM * KDIM;
    for (int idx = tid; idx < KDIM * KDIM; idx += 256) {
        int a = idx >> 7, b = idx & 127;
        float s = G[idx] * rn - s_mu[a] * s_mu[b] + (a == b ? 1.0f : 0.0f);
        sS[a * SPC + b] = s;
        Sg[idx] = s;
    }
    __syncthreads();

    // ---- blocked right-looking Cholesky, NB=32 ----
    for (int kb = 0; kb < KDIM / NB; kb++) {
        const int c0 = kb * NB;

        if (tid < 32) {
            const int lane = tid;
            const int row = c0 + lane;
            float a[NB];
#pragma unroll
            for (int m = 0; m < NB; m++) a[m] = sS[row * SPC + c0 + m];
#pragma unroll
            for (int j = 0; j < NB; j++) {
                float piv = __shfl_sync(0xffffffffu, a[j], j);
                float d = sqrtf(piv);
                float rd = 1.0f / d;
                if (lane == j) { a[j] = d; sRD[c0 + j] = rd; }
                else if (lane > j) a[j] *= rd;
                float lj = a[j];
#pragma unroll
                for (int m = j + 1; m < NB; m++) {
                    float lmj = __shfl_sync(0xffffffffu, lj, m);
                    if (lane >= m) a[m] -= lj * lmj;
                }
            }
#pragma unroll
            for (int m = 0; m < NB; m++)
                if (lane >= m) sS[row * SPC + c0 + m] = a[m];
        }
        __syncthreads();

        const int M = KDIM - c0 - NB;

        if (tid < M) {
            const int r = c0 + NB + tid;
            float x[NB];
#pragma unroll
            for (int j = 0; j < NB; j++) {
                float s = sS[r * SPC + c0 + j];
                float s1 = 0.0f;
#pragma unroll
                for (int m = 0; m + 1 < j; m += 2) {
                    s  -= x[m]     * sS[(c0 + j) * SPC + c0 + m];
                    s1 -= x[m + 1] * sS[(c0 + j) * SPC + c0 + m + 1];
                }
                if (j & 1) s -= x[j - 1] * sS[(c0 + j) * SPC + c0 + j - 1];
                s = (s + s1) * sRD[c0 + j];
                x[j] = s;
                sS[r * SPC + c0 + j] = s;
                sPT[j * PPITCH + tid] = s;
            }
        }
        __syncthreads();

        if (M > 0) {
            const int T = M >> 2;
            const int ntile = T * (T + 1) / 2;
            const int r0 = c0 + NB;
            for (int t = tid; t < ntile; t += 256) {
                int tI = (int)(sqrtf(2.0f * t + 0.25f) - 0.5f);
                while ((tI + 1) * (tI + 2) / 2 <= t) tI++;
                while (tI * (tI + 1) / 2 > t) tI--;
                int tJ = t - tI * (tI + 1) / 2;
                int i0 = tI * 4, j0 = tJ * 4;
                float acc[4][4];
#pragma unroll
                for (int u = 0; u < 4; u++)
#pragma unroll
                    for (int v = 0; v < 4; v++) acc[u][v] = 0.0f;
                for (int m = 0; m < NB; m++) {
                    float4 av = *(const float4*)&sPT[m * PPITCH + i0];
                    float4 bv = *(const float4*)&sPT[m * PPITCH + j0];
                    float aa[4] = {av.x, av.y, av.z, av.w};
                    float bb[4] = {bv.x, bv.y, bv.z, bv.w};
#pragma unroll
                    for (int u = 0; u < 4; u++)
#pragma unroll
                        for (int v = 0; v < 4; v++)
                            acc[u][v] = fmaf(aa[u], bb[v], acc[u][v]);
                }
#pragma unroll
                for (int u = 0; u < 4; u++)
#pragma unroll
                    for (int v = 0; v < 4; v++)
                        sS[(r0 + i0 + u) * SPC + r0 + j0 + v] -= acc[u][v];
            }
        }
        __syncthreads();
    }

    // log2 det
    float v = (tid < KDIM) ? log2f(sS[tid * SPC + tid]) : 0.0f;
    sred[tid] = v;
    __syncthreads();
    for (int s = 128; s; s >>= 1) { if (tid < s) sred[tid] += sred[tid + s]; __syncthreads(); }
    if (tid == 0) g_ld2[c] = 2.0f * sred[0];

    // store L (lower triangle valid; upper garbage never read)
    float* Lg = g_L + (size_t)c * KDIM * KDIM;
    for (int idx = tid; idx < KDIM * KDIM; idx += 256) {
        int a = idx >> 7, b = idx & 127;
        Lg[idx] = sS[a * SPC + b];
    }
}

// ---------------- K3b: blocked triangular inverse, Y = L^{-1} --------------
// grid (4, CLS): blockIdx.x = column-block J, blockIdx.y = class
__global__ __launch_bounds__(256, 1) void k_inv() {
    __shared__ float sT[4][NB * TP];    // diag-block inverses (I = J..3)
    __shared__ float sYb[4][NB * TP];   // Y blocks of this column-block
    __shared__ float sL[NB * TP];
    __shared__ float sC[NB * TP];

    const int J = blockIdx.x, c = blockIdx.y;
    const int tid = threadIdx.x;
    const int nb = 4 - J;               // number of row blocks
    const float* Lg = g_L + (size_t)c * KDIM * KDIM;

    // stage diag blocks L_II (I = J..3) into sT
    for (int bi = 0; bi < nb; bi++) {
        int I = J + bi;
        const float* Lb = Lg + (32 * I) * KDIM + 32 * I;
        for (int idx = tid; idx < 1024; idx += 256) {
            int r = idx >> 5, m = idx & 31;
            sT[bi][r * TP + m] = Lb[r * KDIM + m];
        }
    }
    __syncthreads();

    // in-warp inversion of each 32x32 lower-triangular diag block
    {
        int w = tid >> 5, lane = tid & 31;
        if (w < nb) {
            float* T = sT[w];
            float t[32], y[32];
#pragma unroll
            for (int m = 0; m < 32; m++) t[m] = (m <= lane) ? T[lane * TP + m] : 0.0f;
            float rd = 1.0f / T[lane * TP + lane];
#pragma unroll
            for (int cc = 0; cc < 32; cc++) y[cc] = (cc == lane) ? 1.0f : 0.0f;
            __syncwarp();
#pragma unroll
            for (int m = 0; m < 32; m++) {
                if (lane == m) {
#pragma unroll
                    for (int cc = 0; cc <= m; cc++) y[cc] *= rd;
                }
                float tm = t[m];
                bool act = (lane > m);
#pragma unroll
                for (int cc = 0; cc <= m; cc++) {
                    float ymc = __shfl_sync(0xffffffffu, y[cc], m);
                    if (act) y[cc] -= tm * ymc;
                }
            }
#pragma unroll
            for (int cc = 0; cc < 32; cc++) T[lane * TP + cc] = y[cc];
        }
    }
    __syncthreads();

    // Y_JJ = Tinv_J
    for (int idx = tid; idx < 1024; idx += 256) {
        int r = idx >> 5, m = idx & 31;
        sYb[0][r * TP + m] = sT[0][r * TP + m];
    }
    __syncthreads();

    // off-diagonal blocks: Y_IJ = -Tinv_I * (sum_{k=J}^{I-1} L_Ik * Y_kJ)
    const int r = tid >> 3, c4 = (tid & 7) << 2;
    for (int bi = 1; bi < nb; bi++) {
        int I = J + bi;
        float4 acc = make_float4(0.f, 0.f, 0.f, 0.f);
        for (int bk = 0; bk < bi; bk++) {
            int k = J + bk;
            const float* Lb = Lg + (32 * I) * KDIM + 32 * k;
            for (int idx = tid; idx < 1024; idx += 256) {
                int rr = idx >> 5, mm = idx & 31;
                sL[rr * TP + mm] = Lb[rr * KDIM + mm];
            }
            __syncthreads();
#pragma unroll
            for (int m = 0; m < 32; m++) {
                float a = sL[r * TP + m];
                float4 b = *(const float4*)&sYb[bk][m * TP + c4];
                acc.x = fmaf(a, b.x, acc.x);
                acc.y = fmaf(a, b.y, acc.y);
                acc.z = fmaf(a, b.z, acc.z);
                acc.w = fmaf(a, b.w, acc.w);
            }
            __syncthreads();
        }
        *(float4*)&sC[r * TP + c4] = acc;
        __syncthreads();
        float4 o = make_float4(0.f, 0.f, 0.f, 0.f);
#pragma unroll
        for (int m = 0; m < 32; m++) {
            float a = sT[bi][r * TP + m];
            float4 b = *(const float4*)&sC[m * TP + c4];
            o.x = fmaf(-a, b.x, o.x);
            o.y = fmaf(-a, b.y, o.y);
            o.z = fmaf(-a, b.z, o.z);
            o.w = fmaf(-a, b.w, o.w);
        }
        *(float4*)&sYb[bi][r * TP + c4] = o;
        __syncthreads();
    }

    // store transposed: g_Yt[class][col][row] = Y[row][col]
    float* Yt = g_Yt + (size_t)c * KDIM * KDIM;
    for (int bi = 0; bi < nb; bi++) {
        int I = J + bi;
        for (int idx = tid; idx < 1024; idx += 256) {
            int cc = idx >> 5, rr = idx & 31;
            Yt[(32 * J + cc) * KDIM + 32 * I + rr] = sYb[bi][rr * TP + cc];
        }
    }
}

// ---------------- K3c: inv = Y^T Y (one CTA per class) ---------------------
__global__ __launch_bounds__(256, 1) void k_yty() {
    extern __shared__ float sYt[];       // KDIM * YP
    const int c = blockIdx.x, tid = threadIdx.x;
    const float* Yt = g_Yt + (size_t)c * KDIM * KDIM;

    for (int idx = tid; idx < KDIM * KDIM / 4; idx += 256) {
        int a = idx >> 5, m4 = (idx & 31) << 2;
        *(float4*)&sYt[a * YP + m4] = *(const float4*)&Yt[a * KDIM + m4];
    }
    __syncthreads();

    float* Ig = g_inv + (size_t)c * KDIM * KDIM;
    const int T = KDIM >> 2;
    const int ntile = T * (T + 1) / 2;    // 528
    for (int t = tid; t < ntile; t += 256) {
        int tB = (int)(sqrtf(2.0f * t + 0.25f) - 0.5f);
        while ((tB + 1) * (tB + 2) / 2 <= t) tB++;
        while (tB * (tB + 1) / 2 > t) tB--;
        int tS = t - tB * (tB + 1) / 2;
        int a0 = tS * 4, b0 = tB * 4;     // b0 >= a0
        float acc[4][4];
#pragma unroll
        for (int u = 0; u < 4; u++)
#pragma unroll
            for (int v = 0; v < 4; v++) acc[u][v] = 0.0f;
        for (int m = b0; m < KDIM; m += 4) {
            float4 A[4], B[4];
#pragma unroll
            for (int u = 0; u < 4; u++) A[u] = *(const float4*)&sYt[(a0 + u) * YP + m];
#pragma unroll
            for (int v = 0; v < 4; v++) B[v] = *(const float4*)&sYt[(b0 + v) * YP + m];
#pragma unroll
            for (int u = 0; u < 4; u++)
#pragma unroll
                for (int v = 0; v < 4; v++)
                    acc[u][v] += A[u].x * B[v].x + A[u].y * B[v].y
                               + A[u].z * B[v].z + A[u].w * B[v].w;
        }
#pragma unroll
        for (int u = 0; u < 4; u++)
#pragma unroll
            for (int v = 0; v < 4; v++) {
                Ig[(a0 + u) * KDIM + (b0 + v)] = acc[u][v];
                Ig[(b0 + v) * KDIM + (a0 + u)] = acc[u][v];
            }
    }
}

// ---------------- K4: pairwise KL + mask + final reduction -----------------
__global__ void k_final(float* out) {
    int i = blockIdx.x >> 5, j = blockIdx.x & 31;
    int tid = threadIdx.x;
    __shared__ float sv[KDIM];
    __shared__ float2 sred[256];
    __shared__ int smask;

    if (tid == 0) {
        int fi = g_first[i], fj = g_first[j], ri = 0, rj = 0;
        for (int c = 0; c < CLS; c++) { int f = g_first[c]; ri += (f < fi); rj += (f < fj); }
        smask = (ri <= CLS - 2) && (rj >= 1);
    }
    if (tid < KDIM) sv[tid] = g_mu[i * KDIM + tid] - g_mu[j * KDIM + tid];
    __syncthreads();

    float tr = 0.0f, qd = 0.0f;
    if (smask) {
        const float* Sp = g_S + (size_t)i * KDIM * KDIM;
        const float* Ip = g_inv + (size_t)j * KDIM * KDIM;
        for (int idx = tid; idx < KDIM * KDIM; idx += 256) {
            float w = Ip[idx];
            tr += w * Sp[idx];
            qd += w * sv[idx >> 7] * sv[idx & 127];
        }
    }
    sred[tid] = make_float2(tr, qd);
    __syncthreads();
    for (int s = 128; s; s >>= 1) {
        if (tid < s) { sred[tid].x += sred[tid + s].x; sred[tid].y += sred[tid + s].y; }
        __syncthreads();
    }
    if (tid == 0 && smask) {
        float kl = 0.5f * ((g_ld2[j] - g_ld2[i]) - (float)KDIM + sred[0].y + sred[0].x);
        atomicAdd(out, kl);
    }

    if (blockIdx.x == 0) {
        __syncthreads();
        float m2 = 0.0f;
        for (int idx = tid; idx < CLS * KDIM; idx += 256) { float m = g_mu[idx]; m2 += m * m; }
        sred[tid].x = m2;
        __syncthreads();
        for (int s = 128; s; s >>= 1) { if (tid < s) sred[tid].x += sred[tid + s].x; __syncthreads(); }
        if (tid == 0) atomicAdd(out, -sred[0].x);
    }
}

// ---------------- launch ----------------
extern "C" void kernel_launch(void* const* d_in, const int* in_sizes, int n_in,
                              void* d_out, int out_size) {
    const float* feat = (const float*)d_in[0];
    const int*   lab  = (const int*)d_in[1];
    float* out = (float*)d_out;

    const int CHOLA_SMEM = KDIM * SPC * (int)sizeof(float);   // 66048
    const int YTY_SMEM   = KDIM * YP * (int)sizeof(float);    // 67584
    cudaFuncSetAttribute(k_cholA, cudaFuncAttributeMaxDynamicSharedMemorySize, CHOLA_SMEM);
    cudaFuncSetAttribute(k_yty,  cudaFuncAttributeMaxDynamicSharedMemorySize, YTY_SMEM);

    k_init<<<(CLS * KDIM * KDIM + 255) / 256, 256>>>(out);
    k_sums<<<BATCH / 256, 256>>>(feat, lab);
    k_scatter<<<dim3(RCHUNK, CLS), 256>>>(feat, lab);
    k_cholA<<<CLS, 256, CHOLA_SMEM>>>();
    k_inv<<<dim3(4, CLS), 256>>>();
    k_yty<<<CLS, 256, YTY_SMEM>>>();
    k_final<<<CLS * CLS, 256>>>(out);
}

// round 4
// speedup vs baseline: 2.1510x; 1.3145x over previous
#include <cuda_runtime.h>
#include <cuda_bf16.h>
#include <math.h>

#define BATCH 16384
#define KDIM 128
#define CLS 32
#define PL 132             // sS pitch (float4-aligned, conflict-benign)
#define PW 68              // 64-block buffer pitch
#define P3 36              // 32-block buffer pitch
#define RCHUNK 8
#define ROWS_PER_CHUNK (BATCH / RCHUNK)   // 2048

// ---------------- scratch (device globals: allocation-free) ----------------
__device__ float g_sum[CLS * KDIM];
__device__ int   g_cnt[CLS];
__device__ int   g_first[CLS];
__device__ float g_G[CLS * KDIM * KDIM];    // per-class Gram sums
__device__ float g_S[CLS * KDIM * KDIM];    // per-class scatter+I
__device__ float g_inv[CLS * KDIM * KDIM];  // per-class inverse
__device__ float g_mu[CLS * KDIM];
__device__ float g_ld2[CLS];

// ---------------- K0: zero scratch + output ----------------
__global__ void k_init(float* out) {
    int i = blockIdx.x * blockDim.x + threadIdx.x;
    if (i < CLS * KDIM * KDIM) g_G[i] = 0.0f;
    if (i < CLS * KDIM) g_sum[i] = 0.0f;
    if (i < CLS) { g_cnt[i] = 0; g_first[i] = BATCH; }
    if (i == 0) out[0] = 0.0f;
}

// ---------------- K1: class sums, counts, first occurrence ----------------
__global__ void k_sums(const float* __restrict__ feat, const int* __restrict__ lab) {
    __shared__ float ssum[CLS * KDIM];   // 16 KB
    __shared__ int   scnt[CLS];
    int tid = threadIdx.x;               // 256 threads
    for (int i = tid; i < CLS * KDIM; i += 256) ssum[i] = 0.0f;
    if (tid < CLS) scnt[tid] = 0;
    __syncthreads();

    int warp = tid >> 5, lane = tid & 31;
    int r0 = blockIdx.x * 256 + warp * 32;   // 64 blocks x 256 rows
    for (int r = r0; r < r0 + 32; r++) {
        int c = lab[r];
        if (lane == 0) { atomicAdd(&scnt[c], 1); atomicMin(&g_first[c], r); }
        float4 v = ((const float4*)(feat + (size_t)r * KDIM))[lane];
        float* dst = &ssum[c * KDIM + lane * 4];
        atomicAdd(dst + 0, v.x);
        atomicAdd(dst + 1, v.y);
        atomicAdd(dst + 2, v.z);
        atomicAdd(dst + 3, v.w);
    }
    __syncthreads();
    for (int i = tid; i < CLS * KDIM; i += 256) atomicAdd(&g_sum[i], ssum[i]);
    if (tid < CLS) atomicAdd(&g_cnt[tid], scnt[tid]);
}

// ---------------- K2: per-class Gram accumulation G_c = sum x x^T ----------
__global__ __launch_bounds__(256) void k_scatter(const float* __restrict__ feat,
                                                 const int* __restrict__ lab) {
    const int c = blockIdx.y;
    const int chunk = blockIdx.x;
    const int R0 = chunk * ROWS_PER_CHUNK;
    __shared__ int s_idx[ROWS_PER_CHUNK];
    __shared__ int s_n;
    __shared__ __align__(16) float s_x[16][KDIM];
    int tid = threadIdx.x;
    if (tid == 0) s_n = 0;
    __syncthreads();

    for (int r = R0 + tid; r < R0 + ROWS_PER_CHUNK; r += 256) {
        if (lab[r] == c) { int p = atomicAdd(&s_n, 1); s_idx[p] = r; }
    }
    __syncthreads();
    int n = s_n;

    float acc[8][8];
#pragma unroll
    for (int u = 0; u < 8; u++)
#pragma unroll
        for (int v = 0; v < 8; v++) acc[u][v] = 0.0f;

    int ty = tid >> 4, tx = tid & 15;

    for (int t = 0; t < n; t += 16) {
        int m = min(16, n - t);
        for (int i = tid; i < m * 32; i += 256) {
            int rr = i >> 5, q = i & 31;
            ((float4*)s_x[rr])[q] =
                ((const float4*)(feat + (size_t)s_idx[t + rr] * KDIM))[q];
        }
        __syncthreads();
        for (int e = 0; e < m; e++) {
            float a[8], b[8];
#pragma unroll
            for (int u = 0; u < 8; u++) { a[u] = s_x[e][ty * 8 + u]; b[u] = s_x[e][tx * 8 + u]; }
#pragma unroll
            for (int u = 0; u < 8; u++)
#pragma unroll
                for (int v = 0; v < 8; v++) acc[u][v] = fmaf(a[u], b[v], acc[u][v]);
        }
        __syncthreads();
    }

    if (n > 0) {
        float* G = g_G + (size_t)c * KDIM * KDIM;
#pragma unroll
        for (int u = 0; u < 8; u++)
#pragma unroll
            for (int v = 0; v < 8; v++)
                atomicAdd(&G[(ty * 8 + u) * KDIM + (tx * 8 + v)], acc[u][v]);
    }
}

// ---------------- warp Gauss-Jordan inverse of SPD 32x32 (in-place) --------
// One warp; lane L holds row L in registers. Also accumulates log2(det).
__device__ __forceinline__ void gj32(float* M, int P, float* ldacc) {
    const int lane = threadIdx.x & 31;
    float y[32];
#pragma unroll
    for (int m = 0; m < 32; m++) y[m] = M[lane * P + m];
    float ld = 0.0f;
#pragma unroll
    for (int j = 0; j < 32; j++) {
        float pj = __shfl_sync(0xffffffffu, y[j], j);
        float r = __fdividef(1.0f, pj);
        ld += log2f(pj);
        float c = y[j];
        if (lane == j) {
#pragma unroll
            for (int m = 0; m < 32; m++) y[m] *= r;
            y[j] = r;
        }
#pragma unroll
        for (int m = 0; m < 32; m++) {
            float rowj = __shfl_sync(0xffffffffu, y[m], j);
            if (lane != j && m != j) y[m] -= c * rowj;
        }
        if (lane != j) y[j] = -c * r;
    }
#pragma unroll
    for (int m = 0; m < 32; m++) M[lane * P + m] = y[m];
    if (lane == 0) *ldacc += ld;
}

// ---------------- smem GEMM: O = c0s*C0 + sgn * op(P)·Q  (256 threads) -----
// TRA=false: P[i][m];  TRA=true: P[m][i].  Q always Q[m][j].
template<int N, bool TRA>
__device__ __forceinline__ void sgemm(const float* __restrict__ P, int pp,
                                      const float* __restrict__ Q, int pq,
                                      float* O, int po,
                                      const float* C0, int pc,
                                      float c0s, float sgn) {
    constexpr int T = N / 16;            // 4 for N=64, 2 for N=32
    const int ty = threadIdx.x >> 4, tx = threadIdx.x & 15;
    float acc[T][T];
#pragma unroll
    for (int u = 0; u < T; u++)
#pragma unroll
        for (int v = 0; v < T; v++) acc[u][v] = 0.0f;
#pragma unroll 8
    for (int m = 0; m < N; m++) {
        float a[T], b[T];
#pragma unroll
        for (int u = 0; u < T; u++)
            a[u] = TRA ? P[m * pp + ty * T + u] : P[(ty * T + u) * pp + m];
#pragma unroll
        for (int v = 0; v < T; v++) b[v] = Q[m * pq + tx * T + v];
#pragma unroll
        for (int u = 0; u < T; u++)
#pragma unroll
            for (int v = 0; v < T; v++) acc[u][v] = fmaf(a[u], b[v], acc[u][v]);
    }
#pragma unroll
    for (int u = 0; u < T; u++)
#pragma unroll
        for (int v = 0; v < T; v++) {
            float o = sgn * acc[u][v];
            if (C0) o += c0s * C0[(ty * T + u) * pc + tx * T + v];
            O[(ty * T + u) * po + tx * T + v] = o;
        }
}

// ---------------- 64x64 SPD inverse via one-level Schur (in place) ---------
// M: 64x64 block at pitch pm. w,t,u: 32x36 scratch. Adds log2det to *ldacc.
__device__ void inv64(float* M, int pm, float* ldacc,
                      float* w, float* t, float* u) {
    if (threadIdx.x < 32) gj32(M, pm, ldacc);               // a -> inva
    __syncthreads();
    sgemm<32, false>(M + 32 * pm, pm, M, pm, w, P3, (const float*)0, 0, 0.f, 1.f);  // w = b·inva
    __syncthreads();
    sgemm<32, false>(w, P3, M + 32, pm, t, P3, M + 32 * pm + 32, pm, 1.f, -1.f);    // t = c - w·b^T
    __syncthreads();
    if (threadIdx.x < 32) gj32(t, P3, ldacc);               // t -> invt
    __syncthreads();
    sgemm<32, false>(t, P3, w, P3, u, P3, (const float*)0, 0, 0.f, 1.f);            // u = invt·w
    __syncthreads();
    sgemm<32, true>(w, P3, u, P3, M, pm, M, pm, 1.f, 1.f);  // M00 = inva + w^T·u
    for (int idx = threadIdx.x; idx < 32 * 32; idx += 256) {
        int i = idx >> 5, j = idx & 31;
        M[(32 + i) * pm + 32 + j] = t[i * P3 + j];
        M[(32 + i) * pm + j]      = -u[i * P3 + j];
        M[i * pm + 32 + j]        = -u[j * P3 + i];
    }
    __syncthreads();
}

// ---------------- K3: per-class S, S^{-1} (Schur D&C), log2det -------------
__global__ __launch_bounds__(256, 1) void k_sinv() {
    extern __shared__ float sm[];
    float* sS  = sm;                       // 128 * PL
    float* sW  = sS + KDIM * PL;           // 64 * PW
    float* sT  = sW + 64 * PW;             // 64 * PW
    float* sU  = sT + 64 * PW;             // 64 * PW
    float* s3a = sU + 64 * PW;             // 32 * P3
    float* s3b = s3a + 32 * P3;
    float* s3c = s3b + 32 * P3;
    __shared__ float s_mu[KDIM];
    __shared__ float s_ld;

    const int c = blockIdx.x, tid = threadIdx.x;

    float n = (float)g_cnt[c];
    float rn = 1.0f / n;
    if (tid < KDIM) {
        float m = g_sum[c * KDIM + tid] * rn;
        s_mu[tid] = m;
        g_mu[c * KDIM + tid] = m;
    }
    if (tid == 0) s_ld = 0.0f;
    __syncthreads();

    // build S = G/n - mu mu^T + I (into smem + g_S)
    const float* G = g_G + (size_t)c * KDIM * KDIM;
    float* Sg = g_S + (size_t)c * KDIM * KDIM;
    for (int idx = tid; idx < KDIM * KDIM; idx += 256) {
        int a = idx >> 7, b = idx & 127;
        float s = G[idx] * rn - s_mu[a] * s_mu[b] + (a == b ? 1.0f : 0.0f);
        sS[a * PL + b] = s;
        Sg[idx] = s;
    }
    __syncthreads();

    // ---- S = [[A, Bt],[B, C]] ; two-level Schur inverse ----
    inv64(sS, PL, &s_ld, s3a, s3b, s3c);                     // A -> invA
    // W = B·invA
    sgemm<64, false>(sS + 64 * PL, PL, sS, PL, sW, PW, (const float*)0, 0, 0.f, 1.f);
    __syncthreads();
    // T = C - W·B^T   (B^T taken from stored symmetric top-right block)
    sgemm<64, false>(sW, PW, sS + 64, PL, sT, PW, sS + 64 * PL + 64, PL, 1.f, -1.f);
    __syncthreads();
    inv64(sT, PW, &s_ld, s3a, s3b, s3c);                     // T -> invT
    // U = invT·W
    sgemm<64, false>(sT, PW, sW, PW, sU, PW, (const float*)0, 0, 0.f, 1.f);
    __syncthreads();
    // top-left = invA + W^T·U ; other blocks assembled elementwise
    sgemm<64, true>(sW, PW, sU, PW, sS, PL, sS, PL, 1.f, 1.f);
    for (int idx = tid; idx < 64 * 64; idx += 256) {
        int i = idx >> 6, j = idx & 63;
        sS[(64 + i) * PL + 64 + j] = sT[i * PW + j];
        sS[(64 + i) * PL + j]      = -sU[i * PW + j];
        sS[i * PL + 64 + j]        = -sU[j * PW + i];
    }
    __syncthreads();

    // dump inverse + logdet
    float* Ig = g_inv + (size_t)c * KDIM * KDIM;
    for (int idx = tid; idx < KDIM * KDIM / 4; idx += 256) {
        int a = idx >> 5, b4 = (idx & 31) << 2;
        *(float4*)&Ig[a * KDIM + b4] = *(const float4*)&sS[a * PL + b4];
    }
    if (tid == 0) g_ld2[c] = s_ld;
}

// ---------------- K4: pairwise KL + mask + final reduction -----------------
__global__ void k_final(float* out) {
    int i = blockIdx.x >> 5, j = blockIdx.x & 31;
    int tid = threadIdx.x;
    __shared__ float sv[KDIM];
    __shared__ float2 sred[256];
    __shared__ int smask;

    if (tid == 0) {
        int fi = g_first[i], fj = g_first[j], ri = 0, rj = 0;
        for (int c = 0; c < CLS; c++) { int f = g_first[c]; ri += (f < fi); rj += (f < fj); }
        smask = (ri <= CLS - 2) && (rj >= 1);
    }
    if (tid < KDIM) sv[tid] = g_mu[i * KDIM + tid] - g_mu[j * KDIM + tid];
    __syncthreads();

    float tr = 0.0f, qd = 0.0f;
    if (smask) {
        const float* Sp = g_S + (size_t)i * KDIM * KDIM;
        const float* Ip = g_inv + (size_t)j * KDIM * KDIM;
        for (int idx = tid; idx < KDIM * KDIM; idx += 256) {
            float w = Ip[idx];
            tr += w * Sp[idx];
            qd += w * sv[idx >> 7] * sv[idx & 127];
        }
    }
    sred[tid] = make_float2(tr, qd);
    __syncthreads();
    for (int s = 128; s; s >>= 1) {
        if (tid < s) { sred[tid].x += sred[tid + s].x; sred[tid].y += sred[tid + s].y; }
        __syncthreads();
    }
    if (tid == 0 && smask) {
        float kl = 0.5f * ((g_ld2[j] - g_ld2[i]) - (float)KDIM + sred[0].y + sred[0].x);
        atomicAdd(out, kl);
    }

    if (blockIdx.x == 0) {
        __syncthreads();
        float m2 = 0.0f;
        for (int idx = tid; idx < CLS * KDIM; idx += 256) { float m = g_mu[idx]; m2 += m * m; }
        sred[tid].x = m2;
        __syncthreads();
        for (int s = 128; s; s >>= 1) { if (tid < s) sred[tid].x += sred[tid + s].x; __syncthreads(); }
        if (tid == 0) atomicAdd(out, -sred[0].x);
    }
}

// ---------------- launch ----------------
extern "C" void kernel_launch(void* const* d_in, const int* in_sizes, int n_in,
                              void* d_out, int out_size) {
    const float* feat = (const float*)d_in[0];
    const int*   lab  = (const int*)d_in[1];
    float* out = (float*)d_out;

    const int SINV_SMEM = (KDIM * PL + 3 * 64 * PW + 3 * 32 * P3) * (int)sizeof(float); // 133632
    cudaFuncSetAttribute(k_sinv, cudaFuncAttributeMaxDynamicSharedMemorySize, SINV_SMEM);

    k_init<<<(CLS * KDIM * KDIM + 255) / 256, 256>>>(out);
    k_sums<<<BATCH / 256, 256>>>(feat, lab);
    k_scatter<<<dim3(RCHUNK, CLS), 256>>>(feat, lab);
    k_sinv<<<CLS, 256, SINV_SMEM>>>();
    k_final<<<CLS * CLS, 256>>>(out);
}